// round 6
// baseline (speedup 1.0000x reference)
#include <cuda_runtime.h>
#include <math.h>

// ---------------- problem constants ----------------
#define SEQ   256
#define BATCH 2
#define HIDD  512
#define NHEAD 8
#define HDIM  64
#define NROW  512              // BATCH*SEQ
#define CHB   2048             // chunks per batch = SEQ*NHEAD
#define EPSN  1e-15f
#define MAXNORM 0.996f         // (1-4e-3)/sqrt(c), c=1

// ---------------- device scratch (static, allowed) ----------------
__device__ float g_mx[3 * NROW * HIDD];        // GEMM outputs (3 MB)
__device__ float g_q[NROW * HIDD];             // ql chunks, flat [b][s'][512]
__device__ float g_k[NROW * HIDD];
__device__ float g_v[NROW * HIDD];
__device__ float g_q2[BATCH * CHB];            // |ql chunk|^2
__device__ float g_k2[BATCH * CHB];
__device__ float g_gamma[BATCH * CHB];         // 2/max(1-|vl|^2,eps)
__device__ float g_pnom[4 * NROW * HIDD];      // ctx partial numerators (4 MB)
__device__ float g_pdac[4 * NROW * NHEAD];     // ctx partial denominators
__device__ float g_probs[BATCH * NHEAD * SEQ * SEQ]; // fallback if out lacks probs

// ---------------- packed f32x2 helpers (sm_100+/sm_103a FFMA2 path) ----------------
__device__ __forceinline__ float2 ffma2(float2 a, float2 b, float2 c) {
    unsigned long long ua = *(unsigned long long*)&a;
    unsigned long long ub = *(unsigned long long*)&b;
    unsigned long long uc = *(unsigned long long*)&c;
    unsigned long long ud;
    asm("fma.rn.f32x2 %0, %1, %2, %3;" : "=l"(ud) : "l"(ua), "l"(ub), "l"(uc));
    return *(float2*)&ud;
}
__device__ __forceinline__ float2 fmul2(float2 a, float2 b) {
    unsigned long long ua = *(unsigned long long*)&a;
    unsigned long long ub = *(unsigned long long*)&b;
    unsigned long long ud;
    asm("mul.rn.f32x2 %0, %1, %2;" : "=l"(ud) : "l"(ua), "l"(ub));
    return *(float2*)&ud;
}
__device__ __forceinline__ float2 fadd2(float2 a, float2 b) {
    unsigned long long ua = *(unsigned long long*)&a;
    unsigned long long ub = *(unsigned long long*)&b;
    unsigned long long ud;
    asm("add.rn.f32x2 %0, %1, %2;" : "=l"(ud) : "l"(ua), "l"(ub));
    return *(float2*)&ud;
}

__device__ __forceinline__ float atanh_c(float x) {
    x = fminf(fmaxf(x, -0.9999999f), 0.9999999f);
    return atanhf(x);
}
__device__ __forceinline__ float dot4(float4 a, float4 b) {
    return a.x * b.x + a.y * b.y + a.z * b.z + a.w * b.w;
}
__device__ __forceinline__ float blkred(float v, float* sm) {
    #pragma unroll
    for (int o = 16; o; o >>= 1) v += __shfl_xor_sync(0xffffffffu, v, o);
    if ((threadIdx.x & 31) == 0) sm[threadIdx.x >> 5] = v;
    __syncthreads();
    v = sm[0] + sm[1] + sm[2] + sm[3];
    __syncthreads();
    return v;
}

// ================= K1: mx = x @ W^T for q,k,v (packed f32x2) =================
// A row r = b*256+s'  maps to query[(s'*B + b)*512 + k]
__global__ __launch_bounds__(256) void gemm_kernel(
    const float* __restrict__ query,
    const float* __restrict__ Wq,
    const float* __restrict__ Wk,
    const float* __restrict__ Wv)
{
    __shared__ float2 As2[16][68];   // A values duplicated into both lanes
    __shared__ float  Bs[16][68];
    int mat = blockIdx.z;
    const float* W = (mat == 0) ? Wq : (mat == 1 ? Wk : Wv);
    float* out = g_mx + mat * NROW * HIDD;
    int t = threadIdx.x;
    int tx = t & 15, ty = t >> 4;
    int row0 = blockIdx.y << 6, col0 = blockIdx.x << 6;

    float2 acc2[4][2];
    #pragma unroll
    for (int i = 0; i < 4; i++) {
        acc2[i][0] = make_float2(0.f, 0.f);
        acc2[i][1] = make_float2(0.f, 0.f);
    }

    for (int k0 = 0; k0 < HIDD; k0 += 16) {
        #pragma unroll
        for (int li = t; li < 1024; li += 256) {
            int i = li >> 4, kk = li & 15;
            int r = row0 + i;
            float av = query[((((r & 255) << 1) + (r >> 8)) << 9) + k0 + kk];
            As2[kk][i] = make_float2(av, av);
            Bs[kk][i] = W[((col0 + i) << 9) + k0 + kk];
        }
        __syncthreads();
        #pragma unroll
        for (int kk = 0; kk < 16; kk++) {
            float4 b = *(const float4*)&Bs[kk][tx << 2];
            float2 b01 = make_float2(b.x, b.y);
            float2 b23 = make_float2(b.z, b.w);
            #pragma unroll
            for (int i = 0; i < 4; i++) {
                float2 a = As2[kk][(ty << 2) + i];
                acc2[i][0] = ffma2(a, b01, acc2[i][0]);
                acc2[i][1] = ffma2(a, b23, acc2[i][1]);
            }
        }
        __syncthreads();
    }
    #pragma unroll
    for (int i = 0; i < 4; i++) {
        float4 o = {acc2[i][0].x, acc2[i][0].y, acc2[i][1].x, acc2[i][1].y};
        *(float4*)(out + ((row0 + (ty << 2) + i) << 9) + col0 + (tx << 2)) = o;
    }
}

// ===== K2: per-row mobius_matvec norm map + mobius_add bias + projx +
//           logmap0(512) + per-64-chunk expmap0 + chunk stats =====
__global__ __launch_bounds__(128) void epilogue_kernel(
    const float* __restrict__ query,
    const float* __restrict__ bq,
    const float* __restrict__ bk,
    const float* __restrict__ bv)
{
    __shared__ float red[4];
    int bid = blockIdx.x;
    int mat = bid >> 9;          // 0..2
    int r = bid & 511;           // b*256 + s'
    int b = r >> 8, sp = r & 255;
    const float* bias_p = (mat == 0) ? bq : (mat == 1 ? bk : bv);
    float* outp = (mat == 0) ? g_q : (mat == 1 ? g_k : g_v);
    int t = threadIdx.x;

    float4 x  = *(const float4*)(query + ((sp * BATCH + b) << 9) + 4 * t);
    float4 m  = *(const float4*)(g_mx + mat * NROW * HIDD + (r << 9) + 4 * t);
    float4 bi = *(const float4*)(bias_p + 4 * t);

    float sxx = blkred(dot4(x, x), red);
    float smm = blkred(dot4(m, m), red);
    float xn = fmaxf(sqrtf(sxx), EPSN);
    float mn = fmaxf(sqrtf(smm), EPSN);
    float sc1 = tanhf(mn / xn * atanh_c(xn)) / mn;
    float4 res = {sc1 * m.x, sc1 * m.y, sc1 * m.z, sc1 * m.w};

    float x2 = blkred(dot4(res, res), red);
    float xy = blkred(dot4(res, bi), red);
    float y2 = blkred(dot4(bi, bi), red);
    float ac = 1.f + 2.f * xy + y2;
    float bc = 1.f - x2;
    float den = fmaxf(1.f + 2.f * xy + x2 * y2, EPSN);
    float idn = 1.f / den;
    float4 z = {(ac * res.x + bc * bi.x) * idn, (ac * res.y + bc * bi.y) * idn,
                (ac * res.z + bc * bi.z) * idn, (ac * res.w + bc * bi.w) * idn};

    float z2 = blkred(dot4(z, z), red);
    float nz = fmaxf(sqrtf(z2), EPSN);
    float ps = (nz > MAXNORM) ? (MAXNORM / nz) : 1.f;
    float nzc = nz * ps;                       // = min(nz, MAXNORM)
    float us = atanh_c(nzc) / fmaxf(nzc, EPSN) * ps;   // u = us * z
    float4 u = {us * z.x, us * z.y, us * z.z, us * z.w};

    // per-64-chunk expmap0: thread's 4 elems (c=4t..4t+3) are all in chunk t/16
    float cs = dot4(u, u);
    #pragma unroll
    for (int o = 8; o; o >>= 1) cs += __shfl_xor_sync(0xffffffffu, cs, o, 16);
    float cn = fmaxf(sqrtf(cs), EPSN);
    float csc = tanhf(cn) / cn;
    float4 o4 = {csc * u.x, csc * u.y, csc * u.z, csc * u.w};
    *(float4*)(outp + (r << 9) + 4 * t) = o4;

    if ((t & 15) == 0) {
        float o2 = csc * csc * cs;             // |chunk|^2 of output
        int cid = b * CHB + sp * 8 + (t >> 4); // flat chunk id == h*256+s
        if (mat == 0)      g_q2[cid] = o2;
        else if (mat == 1) g_k2[cid] = o2;
        else               g_gamma[cid] = 2.f / fmaxf(1.f - o2, EPSN);
    }
}

// ===== K3: scores -> probs.  64x64 (q,n) tile per block, packed f32x2. =====
// probs = (1 - clip(t1)) / 2   [sigmoid(-2 artanh(t1)) identity]
// t1 = rsqrt(sum_d 1/w_d^2) / den; quad-combine -> 1 RCP per 4 d
__global__ __launch_bounds__(256, 2) void score_kernel(float* __restrict__ probs_ext)
{
    __shared__ float qsm[64][68];
    __shared__ float ksm[64][68];
    __shared__ float q2s[64];
    __shared__ float k2s[64];
    float* probs = probs_ext ? probs_ext : g_probs;

    int bh = blockIdx.z;
    int b = bh >> 3, h = bh & 7;
    int q0 = blockIdx.y << 6, n0 = blockIdx.x << 6;
    const float4* Qp = (const float4*)(g_q + b * 131072 + ((h << 8) + q0) * 64);
    const float4* Kp = (const float4*)(g_k + b * 131072 + ((h << 8) + n0) * 64);
    int t = threadIdx.x;

    for (int li = t; li < 1024; li += 256) {
        int row = li >> 4, c4 = li & 15;
        *(float4*)&qsm[row][c4 << 2] = Qp[li];
        *(float4*)&ksm[row][c4 << 2] = Kp[li];
    }
    if (t < 64) {
        q2s[t] = g_q2[b * CHB + (h << 8) + q0 + t];
        k2s[t] = g_k2[b * CHB + (h << 8) + n0 + t];
    }
    __syncthreads();

    int qi = t >> 2, nl = t & 3;
    float4 qr[16];
    #pragma unroll
    for (int i = 0; i < 16; i++) qr[i] = *(const float4*)&qsm[qi][i << 2];
    float q2 = q2s[qi];
    float Bc = 1.f - q2;
    float2 Bc2 = make_float2(Bc, Bc);
    float* orow = probs + ((bh << 8) + q0 + qi) * 256 + n0;

    #pragma unroll 1
    for (int jj = 0; jj < 8; jj++) {
        int na = (jj << 3) | nl;       // two n per iteration: na, na+4
        int nb = na + 4;
        // ---- pass 1: dot products, packed (4 independent chains) ----
        float2 sa0 = make_float2(0.f, 0.f), sa1 = make_float2(0.f, 0.f);
        float2 sb0 = make_float2(0.f, 0.f), sb1 = make_float2(0.f, 0.f);
        #pragma unroll
        for (int i = 0; i < 16; i++) {
            float4 q = qr[i];
            float4 ka = *(const float4*)&ksm[na][i << 2];
            float4 kb = *(const float4*)&ksm[nb][i << 2];
            sa0 = ffma2(make_float2(q.x, q.y), make_float2(ka.x, ka.y), sa0);
            sa1 = ffma2(make_float2(q.z, q.w), make_float2(ka.z, ka.w), sa1);
            sb0 = ffma2(make_float2(q.x, q.y), make_float2(kb.x, kb.y), sb0);
            sb1 = ffma2(make_float2(q.z, q.w), make_float2(kb.z, kb.w), sb1);
        }
        float da = sa0.x + sa0.y + sa1.x + sa1.y;
        float db = sb0.x + sb0.y + sb1.x + sb1.y;
        float k2a = k2s[na], k2b = k2s[nb];
        float Aa = 1.f - 2.f * da + k2a;
        float Ab = 1.f - 2.f * db + k2b;
        float dena = fmaxf(fmaf(q2, k2a, 1.f - 2.f * da), EPSN);
        float denb = fmaxf(fmaf(q2, k2b, 1.f - 2.f * db), EPSN);
        float2 mAa = make_float2(-Aa, -Aa);
        float2 mAb = make_float2(-Ab, -Ab);
        // ---- pass 2: sum of reciprocal squares, packed quad-combine ----
        float acca = 0.f, accb = 0.f;
        #pragma unroll
        for (int i = 0; i < 16; i++) {
            float4 q = qr[i];
            float2 q01 = make_float2(q.x, q.y);
            float2 q23 = make_float2(q.z, q.w);
            float4 ka = *(const float4*)&ksm[na][i << 2];
            float4 kb = *(const float4*)&ksm[nb][i << 2];
            {
                float2 w01 = ffma2(Bc2, make_float2(ka.x, ka.y), fmul2(mAa, q01));
                float2 w23 = ffma2(Bc2, make_float2(ka.z, ka.w), fmul2(mAa, q23));
                float2 x01 = fmul2(w01, w01);
                float2 x23 = fmul2(w23, w23);
                float2 s2 = fadd2(x01, x23);    // (x0+x2, x1+x3)
                float2 p2 = fmul2(x01, x23);    // (x0*x2, x1*x3)
                float num = fmaf(s2.x, p2.y, s2.y * p2.x);
                float dn4 = fmaxf(p2.x * p2.y, 1e-37f);
                acca += __fdividef(num, dn4);
            }
            {
                float2 w01 = ffma2(Bc2, make_float2(kb.x, kb.y), fmul2(mAb, q01));
                float2 w23 = ffma2(Bc2, make_float2(kb.z, kb.w), fmul2(mAb, q23));
                float2 x01 = fmul2(w01, w01);
                float2 x23 = fmul2(w23, w23);
                float2 s2 = fadd2(x01, x23);
                float2 p2 = fmul2(x01, x23);
                float num = fmaf(s2.x, p2.y, s2.y * p2.x);
                float dn4 = fmaxf(p2.x * p2.y, 1e-37f);
                accb += __fdividef(num, dn4);
            }
        }
        float t1a = __fdividef(rsqrtf(acca), dena);
        float t1b = __fdividef(rsqrtf(accb), denb);
        t1a = fminf(t1a, 0.9999999f);
        t1b = fminf(t1b, 0.9999999f);
        orow[na] = 0.5f - 0.5f * t1a;
        orow[nb] = 0.5f - 0.5f * t1b;
    }
}

// ===== K4: weighted gyro-midpoint partial sums, n split 4-way =====
// block (qt, bh, ns): nom[16q x 64d] += probs[16q x 64n] @ (gamma*v)[64n x 64d]
__global__ __launch_bounds__(256) void ctx_kernel(const float* __restrict__ probs_ext)
{
    __shared__ float  psm[16][64];     // probs tile (broadcast reads)
    __shared__ float4 vsm[64][17];     // gamma*v tile, padded
    __shared__ float  gm1[64];
    const float* probs = probs_ext ? probs_ext : g_probs;

    int bh = blockIdx.y;               // b*8 + h
    int b = bh >> 3, h = bh & 7;
    int q0 = blockIdx.x << 4;          // 16 q rows per block
    int ns = blockIdx.z;               // n-split 0..3 (64 n each)
    int t = threadIdx.x;
    int qi = t >> 4, dh = t & 15;

    const float* Vb  = g_v + b * 131072 + (h << 14);
    const float* gmb = g_gamma + b * CHB + (h << 8);
    const float* pb  = probs + ((bh << 8) + q0) * 256 + (ns << 6);

    // probs tile: 16 rows x 64 n
    for (int li = t; li < 1024; li += 256)
        psm[li >> 6][li & 63] = pb[(li >> 6) * 256 + (li & 63)];
    // gamma*v tile: 64 n x 64 d as float4
    for (int li = t; li < 1024; li += 256) {
        int n = li >> 4, d4 = li & 15;
        int gn = (ns << 6) + n;
        float g = gmb[gn];
        float4 v = *(const float4*)(Vb + (gn << 6) + (d4 << 2));
        vsm[n][d4] = make_float4(v.x * g, v.y * g, v.z * g, v.w * g);
    }
    if (t < 64) gm1[t] = gmb[(ns << 6) + t] - 1.f;
    __syncthreads();

    float4 nomA = {0.f, 0.f, 0.f, 0.f};
    float4 nomB = {0.f, 0.f, 0.f, 0.f};
    float daccA = 0.f, daccB = 0.f;
    #pragma unroll 8
    for (int n = 0; n < 64; n += 2) {
        float p0 = psm[qi][n];
        float p1 = psm[qi][n + 1];
        float4 v0 = vsm[n][dh];
        float4 v1 = vsm[n + 1][dh];
        nomA.x = fmaf(p0, v0.x, nomA.x);
        nomA.y = fmaf(p0, v0.y, nomA.y);
        nomA.z = fmaf(p0, v0.z, nomA.z);
        nomA.w = fmaf(p0, v0.w, nomA.w);
        daccA = fmaf(p0, gm1[n], daccA);
        nomB.x = fmaf(p1, v1.x, nomB.x);
        nomB.y = fmaf(p1, v1.y, nomB.y);
        nomB.z = fmaf(p1, v1.z, nomB.z);
        nomB.w = fmaf(p1, v1.w, nomB.w);
        daccB = fmaf(p1, gm1[n + 1], daccB);
    }
    float4 nom = {nomA.x + nomB.x, nomA.y + nomB.y, nomA.z + nomB.z, nomA.w + nomB.w};
    int row = (b << 8) + q0 + qi;
    *(float4*)(g_pnom + ((ns * NROW + row) << 9) + (h << 6) + (dh << 2)) = nom;
    if (dh == 0)
        g_pdac[((ns * NROW + row) << 3) + h] = daccA + daccB;
}

// ===== K5: reduce partials + gyro epilogue + final expmap0 + transpose =====
__global__ __launch_bounds__(128) void final_kernel(float* __restrict__ out)
{
    __shared__ float red[4];
    int row = blockIdx.x;          // b*256 + q
    int b = row >> 8, q = row & 255;
    int t = threadIdx.x;
    int h = t >> 4;

    float4 nom = {0.f, 0.f, 0.f, 0.f};
    float dacc = 0.f;
    #pragma unroll
    for (int ns = 0; ns < 4; ns++) {
        float4 pv = *(const float4*)(g_pnom + ((ns * NROW + row) << 9) + (t << 2));
        nom.x += pv.x; nom.y += pv.y; nom.z += pv.z; nom.w += pv.w;
        dacc += g_pdac[((ns * NROW + row) << 3) + h];
    }

    // denom sign/floor, ctx0 = nom/denom, then u = 0.5*atanh(|ctx0|)/|ctx0| * ctx0
    float dn = fmaxf(fabsf(dacc), 1e-10f);
    if (dacc < 0.f) dn = -dn;
    float idn = 1.f / dn;
    float4 c0 = {nom.x * idn, nom.y * idn, nom.z * idn, nom.w * idn};
    float ss = dot4(c0, c0);
    #pragma unroll
    for (int o = 8; o; o >>= 1) ss += __shfl_xor_sync(0xffffffffu, ss, o, 16);
    float nn = fmaxf(sqrtf(ss), EPSN);
    float usc = 0.5f * atanh_c(nn) / nn;
    float4 u = {usc * c0.x, usc * c0.y, usc * c0.z, usc * c0.w};

    // full-512 expmap0 + transpose to [S,B,HID]
    float s = blkred(dot4(u, u), red);
    float n512 = fmaxf(sqrtf(s), EPSN);
    float sc = tanhf(n512) / n512;
    float4 o = {sc * u.x, sc * u.y, sc * u.z, sc * u.w};
    *(float4*)(out + ((q * BATCH + b) << 9) + (t << 2)) = o;
}

// ---------------- launch ----------------
extern "C" void kernel_launch(void* const* d_in, const int* in_sizes, int n_in,
                              void* d_out, int out_size)
{
    const float* query = (const float*)d_in[0];
    const float* Wq = (const float*)d_in[1];
    const float* bq = (const float*)d_in[2];
    const float* Wk = (const float*)d_in[3];
    const float* bk = (const float*)d_in[4];
    const float* Wv = (const float*)d_in[5];
    const float* bv = (const float*)d_in[6];
    float* out = (float*)d_out;

    // output layout: ctx [S,B,HID] (262144) then probs [B,H,S,S] (1048576)
    float* probs = (out_size >= 262144 + 1048576) ? (out + 262144) : (float*)0;

    gemm_kernel<<<dim3(8, 8, 3), 256>>>(query, Wq, Wk, Wv);
    epilogue_kernel<<<1536, 128>>>(query, bq, bk, bv);
    score_kernel<<<dim3(4, 4, 16), 256>>>(probs);
    ctx_kernel<<<dim3(16, 16, 4), 256>>>(probs);
    final_kernel<<<512, 128>>>(out);
}

// round 8
// speedup vs baseline: 1.1472x; 1.1472x over previous
#include <cuda_runtime.h>
#include <math.h>

// ---------------- problem constants ----------------
#define SEQ   256
#define BATCH 2
#define HIDD  512
#define NHEAD 8
#define HDIM  64
#define NROW  512              // BATCH*SEQ
#define CHB   2048             // chunks per batch = SEQ*NHEAD
#define EPSN  1e-15f
#define MAXNORM 0.996f         // (1-4e-3)/sqrt(c), c=1

// ---------------- device scratch (static, allowed) ----------------
__device__ float g_mx[3 * NROW * HIDD];        // GEMM outputs (3 MB)
__device__ float g_q[NROW * HIDD];             // ql chunks, flat [b][s'][512]
__device__ float g_k[NROW * HIDD];
__device__ float g_v[NROW * HIDD];
__device__ float g_q2[BATCH * CHB];            // |ql chunk|^2
__device__ float g_k2[BATCH * CHB];
__device__ float g_gamma[BATCH * CHB];         // 2/max(1-|vl|^2,eps)
__device__ float g_pnom[4 * NROW * HIDD];      // ctx partial numerators (4 MB)
__device__ float g_pdac[4 * NROW * NHEAD];     // ctx partial denominators
__device__ float g_probs[BATCH * NHEAD * SEQ * SEQ]; // fallback if out lacks probs

__device__ __forceinline__ float atanh_c(float x) {
    x = fminf(fmaxf(x, -0.9999999f), 0.9999999f);
    return atanhf(x);
}
__device__ __forceinline__ float dot4(float4 a, float4 b) {
    return a.x * b.x + a.y * b.y + a.z * b.z + a.w * b.w;
}
__device__ __forceinline__ float warpsum(float v) {
    #pragma unroll
    for (int o = 16; o; o >>= 1) v += __shfl_xor_sync(0xffffffffu, v, o);
    return v;
}
__device__ __forceinline__ float grp4sum(float v) {   // sum within 4-lane groups
    v += __shfl_xor_sync(0xffffffffu, v, 1, 4);
    v += __shfl_xor_sync(0xffffffffu, v, 2, 4);
    return v;
}
__device__ __forceinline__ float blkred(float v, float* sm) {
    #pragma unroll
    for (int o = 16; o; o >>= 1) v += __shfl_xor_sync(0xffffffffu, v, o);
    if ((threadIdx.x & 31) == 0) sm[threadIdx.x >> 5] = v;
    __syncthreads();
    v = sm[0] + sm[1] + sm[2] + sm[3];
    __syncthreads();
    return v;
}

// ================= K1: mx = x @ W^T for q,k,v (scalar FFMA) =================
// A row r = b*256+s'  maps to query[(s'*B + b)*512 + k]
__global__ __launch_bounds__(256) void gemm_kernel(
    const float* __restrict__ query,
    const float* __restrict__ Wq,
    const float* __restrict__ Wk,
    const float* __restrict__ Wv)
{
    __shared__ float As[16][68];
    __shared__ float Bs[16][68];
    int mat = blockIdx.z;
    const float* W = (mat == 0) ? Wq : (mat == 1 ? Wk : Wv);
    float* out = g_mx + mat * NROW * HIDD;
    int t = threadIdx.x;
    int tx = t & 15, ty = t >> 4;
    int row0 = blockIdx.y << 6, col0 = blockIdx.x << 6;

    float acc[4][4];
    #pragma unroll
    for (int i = 0; i < 4; i++)
        #pragma unroll
        for (int j = 0; j < 4; j++) acc[i][j] = 0.f;

    for (int k0 = 0; k0 < HIDD; k0 += 16) {
        #pragma unroll
        for (int li = t; li < 1024; li += 256) {
            int i = li >> 4, kk = li & 15;
            int r = row0 + i;
            As[kk][i] = query[((((r & 255) << 1) + (r >> 8)) << 9) + k0 + kk];
            Bs[kk][i] = W[((col0 + i) << 9) + k0 + kk];
        }
        __syncthreads();
        #pragma unroll
        for (int kk = 0; kk < 16; kk++) {
            float4 a  = *(const float4*)&As[kk][ty << 2];
            float4 bb = *(const float4*)&Bs[kk][tx << 2];
            float av[4] = {a.x, a.y, a.z, a.w};
            float bv[4] = {bb.x, bb.y, bb.z, bb.w};
            #pragma unroll
            for (int i = 0; i < 4; i++)
                #pragma unroll
                for (int j = 0; j < 4; j++)
                    acc[i][j] = fmaf(av[i], bv[j], acc[i][j]);
        }
        __syncthreads();
    }
    #pragma unroll
    for (int i = 0; i < 4; i++) {
        float4 o = {acc[i][0], acc[i][1], acc[i][2], acc[i][3]};
        *(float4*)(out + ((row0 + (ty << 2) + i) << 9) + col0 + (tx << 2)) = o;
    }
}

// ===== K2: warp-per-row epilogue — shuffle-only reductions, no smem/syncs =====
// mobius_matvec norm map + mobius_add bias + projx + logmap0(512) +
// per-64-chunk expmap0 + chunk stats. Lane l holds elems 16l..16l+15.
__global__ __launch_bounds__(256) void epilogue_kernel(
    const float* __restrict__ query,
    const float* __restrict__ bq,
    const float* __restrict__ bk,
    const float* __restrict__ bv)
{
    int w = blockIdx.x * 8 + (threadIdx.x >> 5);   // global warp = row task
    int l = threadIdx.x & 31;
    int mat = w >> 9;            // 0..2
    int r = w & 511;             // b*256 + s'
    int b = r >> 8, sp = r & 255;
    const float* bias_p = (mat == 0) ? bq : (mat == 1 ? bk : bv);
    float* outp = (mat == 0) ? g_q : (mat == 1 ? g_k : g_v);

    const float4* xp = (const float4*)(query + ((sp * BATCH + b) << 9));
    const float4* mp = (const float4*)(g_mx + mat * NROW * HIDD + (r << 9));
    const float4* bp = (const float4*)bias_p;

    float4 x4[4], m4[4], bi4[4];
    #pragma unroll
    for (int j = 0; j < 4; j++) {
        x4[j]  = xp[4 * l + j];
        m4[j]  = mp[4 * l + j];
        bi4[j] = bp[4 * l + j];
    }

    float sxx = 0.f, smm = 0.f;
    #pragma unroll
    for (int j = 0; j < 4; j++) { sxx += dot4(x4[j], x4[j]); smm += dot4(m4[j], m4[j]); }
    sxx = warpsum(sxx);
    smm = warpsum(smm);
    float xn = fmaxf(sqrtf(sxx), EPSN);
    float mn = fmaxf(sqrtf(smm), EPSN);
    float sc1 = tanhf(mn / xn * atanh_c(xn)) / mn;

    float4 res[4];
    float x2 = 0.f, xy = 0.f, y2 = 0.f;
    #pragma unroll
    for (int j = 0; j < 4; j++) {
        res[j] = make_float4(sc1 * m4[j].x, sc1 * m4[j].y, sc1 * m4[j].z, sc1 * m4[j].w);
        x2 += dot4(res[j], res[j]);
        xy += dot4(res[j], bi4[j]);
        y2 += dot4(bi4[j], bi4[j]);
    }
    x2 = warpsum(x2); xy = warpsum(xy); y2 = warpsum(y2);
    float ac = 1.f + 2.f * xy + y2;
    float bc = 1.f - x2;
    float den = fmaxf(1.f + 2.f * xy + x2 * y2, EPSN);
    float idn = 1.f / den;

    float4 z4[4];
    float z2 = 0.f;
    #pragma unroll
    for (int j = 0; j < 4; j++) {
        z4[j] = make_float4((ac * res[j].x + bc * bi4[j].x) * idn,
                            (ac * res[j].y + bc * bi4[j].y) * idn,
                            (ac * res[j].z + bc * bi4[j].z) * idn,
                            (ac * res[j].w + bc * bi4[j].w) * idn);
        z2 += dot4(z4[j], z4[j]);
    }
    z2 = warpsum(z2);
    float nz = fmaxf(sqrtf(z2), EPSN);
    float ps = (nz > MAXNORM) ? (MAXNORM / nz) : 1.f;
    float nzc = nz * ps;                       // = min(nz, MAXNORM)
    float us = atanh_c(nzc) / fmaxf(nzc, EPSN) * ps;   // u = us * z

    float4 u4[4];
    float cs = 0.f;
    #pragma unroll
    for (int j = 0; j < 4; j++) {
        u4[j] = make_float4(us * z4[j].x, us * z4[j].y, us * z4[j].z, us * z4[j].w);
        cs += dot4(u4[j], u4[j]);
    }
    cs = grp4sum(cs);                          // 64-elem chunk = 4 lanes
    float cn = fmaxf(sqrtf(cs), EPSN);
    float csc = tanhf(cn) / cn;

    float4* op = (float4*)(outp + (r << 9));
    #pragma unroll
    for (int j = 0; j < 4; j++)
        op[4 * l + j] = make_float4(csc * u4[j].x, csc * u4[j].y, csc * u4[j].z, csc * u4[j].w);

    if ((l & 3) == 0) {
        float o2 = csc * csc * cs;             // |chunk|^2 of output
        int cid = b * CHB + sp * 8 + (l >> 2); // flat chunk id == h*256+s
        if (mat == 0)      g_q2[cid] = o2;
        else if (mat == 1) g_k2[cid] = o2;
        else               g_gamma[cid] = 2.f / fmaxf(1.f - o2, EPSN);
    }
}

// ===== K3: scores -> probs.  64x64 (q,n) tile per block, scalar. =====
// probs = (1 - clip(t1)) / 2   [sigmoid(-2 artanh(t1)) identity]
// t1 = rsqrt(sum_d 1/w_d^2) / den; quad-combine -> 1 RCP per 4 d
__global__ __launch_bounds__(256, 2) void score_kernel(float* __restrict__ probs_ext)
{
    __shared__ float qsm[64][68];
    __shared__ float ksm[64][68];
    __shared__ float q2s[64];
    __shared__ float k2s[64];
    float* probs = probs_ext ? probs_ext : g_probs;

    int bh = blockIdx.z;
    int b = bh >> 3, h = bh & 7;
    int q0 = blockIdx.y << 6, n0 = blockIdx.x << 6;
    const float4* Qp = (const float4*)(g_q + b * 131072 + ((h << 8) + q0) * 64);
    const float4* Kp = (const float4*)(g_k + b * 131072 + ((h << 8) + n0) * 64);
    int t = threadIdx.x;

    for (int li = t; li < 1024; li += 256) {
        int row = li >> 4, c4 = li & 15;
        *(float4*)&qsm[row][c4 << 2] = Qp[li];
        *(float4*)&ksm[row][c4 << 2] = Kp[li];
    }
    if (t < 64) {
        q2s[t] = g_q2[b * CHB + (h << 8) + q0 + t];
        k2s[t] = g_k2[b * CHB + (h << 8) + n0 + t];
    }
    __syncthreads();

    int qi = t >> 2, nl = t & 3;
    float4 qr[16];
    #pragma unroll
    for (int i = 0; i < 16; i++) qr[i] = *(const float4*)&qsm[qi][i << 2];
    float q2 = q2s[qi];
    float Bc = 1.f - q2;
    float* orow = probs + ((bh << 8) + q0 + qi) * 256 + n0;

    #pragma unroll 1
    for (int jj = 0; jj < 8; jj++) {
        int na = (jj << 3) | nl;       // two n per iteration: na, na+4
        int nb = na + 4;
        // ---- pass 1: dot products (2 independent chains) ----
        float da = 0.f, db = 0.f;
        #pragma unroll
        for (int i = 0; i < 16; i++) {
            float4 ka = *(const float4*)&ksm[na][i << 2];
            float4 kb = *(const float4*)&ksm[nb][i << 2];
            da += dot4(qr[i], ka);
            db += dot4(qr[i], kb);
        }
        float k2a = k2s[na], k2b = k2s[nb];
        float Aa = 1.f - 2.f * da + k2a;
        float Ab = 1.f - 2.f * db + k2b;
        float dena = fmaxf(fmaf(q2, k2a, 1.f - 2.f * da), EPSN);
        float denb = fmaxf(fmaf(q2, k2b, 1.f - 2.f * db), EPSN);
        // ---- pass 2: sum of reciprocal squares, quad-combined ----
        float acca = 0.f, accb = 0.f;
        #pragma unroll
        for (int i = 0; i < 16; i++) {
            float4 q = qr[i];
            float4 ka = *(const float4*)&ksm[na][i << 2];
            float4 kb = *(const float4*)&ksm[nb][i << 2];
            {
                float w0 = fmaf(Bc, ka.x, -Aa * q.x);
                float w1 = fmaf(Bc, ka.y, -Aa * q.y);
                float w2 = fmaf(Bc, ka.z, -Aa * q.z);
                float w3 = fmaf(Bc, ka.w, -Aa * q.w);
                float x0 = w0 * w0, x1 = w1 * w1, x2 = w2 * w2, x3 = w3 * w3;
                float s01 = x0 + x1, s23 = x2 + x3;
                float p01 = x0 * x1, p23 = x2 * x3;
                float num = fmaf(s01, p23, s23 * p01);
                float dn4 = fmaxf(p01 * p23, 1e-37f);
                acca += __fdividef(num, dn4);
            }
            {
                float w0 = fmaf(Bc, kb.x, -Ab * q.x);
                float w1 = fmaf(Bc, kb.y, -Ab * q.y);
                float w2 = fmaf(Bc, kb.z, -Ab * q.z);
                float w3 = fmaf(Bc, kb.w, -Ab * q.w);
                float x0 = w0 * w0, x1 = w1 * w1, x2 = w2 * w2, x3 = w3 * w3;
                float s01 = x0 + x1, s23 = x2 + x3;
                float p01 = x0 * x1, p23 = x2 * x3;
                float num = fmaf(s01, p23, s23 * p01);
                float dn4 = fmaxf(p01 * p23, 1e-37f);
                accb += __fdividef(num, dn4);
            }
        }
        float t1a = __fdividef(rsqrtf(acca), dena);
        float t1b = __fdividef(rsqrtf(accb), denb);
        t1a = fminf(t1a, 0.9999999f);
        t1b = fminf(t1b, 0.9999999f);
        orow[na] = 0.5f - 0.5f * t1a;
        orow[nb] = 0.5f - 0.5f * t1b;
    }
}

// ===== K4: weighted gyro-midpoint partial sums, n split 4-way =====
// block (qt, bh, ns): nom[16q x 64d] += probs[16q x 64n] @ (gamma*v)[64n x 64d]
__global__ __launch_bounds__(256) void ctx_kernel(const float* __restrict__ probs_ext)
{
    __shared__ float  psm[16][64];     // probs tile (broadcast reads)
    __shared__ float4 vsm[64][17];     // gamma*v tile, padded
    __shared__ float  gm1[64];
    const float* probs = probs_ext ? probs_ext : g_probs;

    int bh = blockIdx.y;               // b*8 + h
    int b = bh >> 3, h = bh & 7;
    int q0 = blockIdx.x << 4;          // 16 q rows per block
    int ns = blockIdx.z;               // n-split 0..3 (64 n each)
    int t = threadIdx.x;
    int qi = t >> 4, dh = t & 15;

    const float* Vb  = g_v + b * 131072 + (h << 14);
    const float* gmb = g_gamma + b * CHB + (h << 8);
    const float* pb  = probs + ((bh << 8) + q0) * 256 + (ns << 6);

    // probs tile: 16 rows x 64 n
    for (int li = t; li < 1024; li += 256)
        psm[li >> 6][li & 63] = pb[(li >> 6) * 256 + (li & 63)];
    // gamma*v tile: 64 n x 64 d as float4
    for (int li = t; li < 1024; li += 256) {
        int n = li >> 4, d4 = li & 15;
        int gn = (ns << 6) + n;
        float g = gmb[gn];
        float4 v = *(const float4*)(Vb + (gn << 6) + (d4 << 2));
        vsm[n][d4] = make_float4(v.x * g, v.y * g, v.z * g, v.w * g);
    }
    if (t < 64) gm1[t] = gmb[(ns << 6) + t] - 1.f;
    __syncthreads();

    float4 nomA = {0.f, 0.f, 0.f, 0.f};
    float4 nomB = {0.f, 0.f, 0.f, 0.f};
    float daccA = 0.f, daccB = 0.f;
    #pragma unroll 8
    for (int n = 0; n < 64; n += 2) {
        float p0 = psm[qi][n];
        float p1 = psm[qi][n + 1];
        float4 v0 = vsm[n][dh];
        float4 v1 = vsm[n + 1][dh];
        nomA.x = fmaf(p0, v0.x, nomA.x);
        nomA.y = fmaf(p0, v0.y, nomA.y);
        nomA.z = fmaf(p0, v0.z, nomA.z);
        nomA.w = fmaf(p0, v0.w, nomA.w);
        daccA = fmaf(p0, gm1[n], daccA);
        nomB.x = fmaf(p1, v1.x, nomB.x);
        nomB.y = fmaf(p1, v1.y, nomB.y);
        nomB.z = fmaf(p1, v1.z, nomB.z);
        nomB.w = fmaf(p1, v1.w, nomB.w);
        daccB = fmaf(p1, gm1[n + 1], daccB);
    }
    float4 nom = {nomA.x + nomB.x, nomA.y + nomB.y, nomA.z + nomB.z, nomA.w + nomB.w};
    int row = (b << 8) + q0 + qi;
    *(float4*)(g_pnom + ((ns * NROW + row) << 9) + (h << 6) + (dh << 2)) = nom;
    if (dh == 0)
        g_pdac[((ns * NROW + row) << 3) + h] = daccA + daccB;
}

// ===== K5: reduce partials + gyro epilogue + final expmap0 + transpose =====
__global__ __launch_bounds__(128) void final_kernel(float* __restrict__ out)
{
    __shared__ float red[4];
    int row = blockIdx.x;          // b*256 + q
    int b = row >> 8, q = row & 255;
    int t = threadIdx.x;
    int h = t >> 4;

    float4 nom = {0.f, 0.f, 0.f, 0.f};
    float dacc = 0.f;
    #pragma unroll
    for (int ns = 0; ns < 4; ns++) {
        float4 pv = *(const float4*)(g_pnom + ((ns * NROW + row) << 9) + (t << 2));
        nom.x += pv.x; nom.y += pv.y; nom.z += pv.z; nom.w += pv.w;
        dacc += g_pdac[((ns * NROW + row) << 3) + h];
    }

    // denom sign/floor, ctx0 = nom/denom, then u = 0.5*atanh(|ctx0|)/|ctx0| * ctx0
    float dn = fmaxf(fabsf(dacc), 1e-10f);
    if (dacc < 0.f) dn = -dn;
    float idn = 1.f / dn;
    float4 c0 = {nom.x * idn, nom.y * idn, nom.z * idn, nom.w * idn};
    float ss = dot4(c0, c0);
    #pragma unroll
    for (int o = 8; o; o >>= 1) ss += __shfl_xor_sync(0xffffffffu, ss, o, 16);
    float nn = fmaxf(sqrtf(ss), EPSN);
    float usc = 0.5f * atanh_c(nn) / nn;
    float4 u = {usc * c0.x, usc * c0.y, usc * c0.z, usc * c0.w};

    // full-512 expmap0 + transpose to [S,B,HID]
    float s = blkred(dot4(u, u), red);
    float n512 = fmaxf(sqrtf(s), EPSN);
    float sc = tanhf(n512) / n512;
    float4 o = {sc * u.x, sc * u.y, sc * u.z, sc * u.w};
    *(float4*)(out + ((q * BATCH + b) << 9) + (t << 2)) = o;
}

// ---------------- launch ----------------
extern "C" void kernel_launch(void* const* d_in, const int* in_sizes, int n_in,
                              void* d_out, int out_size)
{
    const float* query = (const float*)d_in[0];
    const float* Wq = (const float*)d_in[1];
    const float* bq = (const float*)d_in[2];
    const float* Wk = (const float*)d_in[3];
    const float* bk = (const float*)d_in[4];
    const float* Wv = (const float*)d_in[5];
    const float* bv = (const float*)d_in[6];
    float* out = (float*)d_out;

    // output layout: ctx [S,B,HID] (262144) then probs [B,H,S,S] (1048576)
    float* probs = (out_size >= 262144 + 1048576) ? (out + 262144) : (float*)0;

    gemm_kernel<<<dim3(8, 8, 3), 256>>>(query, Wq, Wk, Wv);
    epilogue_kernel<<<192, 256>>>(query, bq, bk, bv);
    score_kernel<<<dim3(4, 4, 16), 256>>>(probs);
    ctx_kernel<<<dim3(16, 16, 4), 256>>>(probs);
    final_kernel<<<512, 128>>>(out);
}

// round 12
// speedup vs baseline: 1.2373x; 1.0786x over previous
#include <cuda_runtime.h>
#include <math.h>

// ---------------- problem constants ----------------
#define SEQ   256
#define BATCH 2
#define HIDD  512
#define NHEAD 8
#define HDIM  64
#define NROW  512              // BATCH*SEQ
#define CHB   2048             // chunks per batch = SEQ*NHEAD
#define EPSN  1e-15f
#define MAXNORM 0.996f         // (1-4e-3)/sqrt(c), c=1

// ---------------- device scratch (static, allowed) ----------------
__device__ float g_mx[3 * NROW * HIDD];        // GEMM outputs (3 MB)
__device__ float g_q[NROW * HIDD];             // ql chunks, flat [b][s'][512]
__device__ float g_k[NROW * HIDD];
__device__ float g_v[NROW * HIDD];
__device__ float g_q2[BATCH * CHB];            // |ql chunk|^2
__device__ float g_k2[BATCH * CHB];
__device__ float g_gamma[BATCH * CHB];         // 2/max(1-|vl|^2,eps)
__device__ float g_pnom[4 * NROW * HIDD];      // ctx partial numerators (4 MB)
__device__ float g_pdac[4 * NROW * NHEAD];     // ctx partial denominators
__device__ float g_probs[BATCH * NHEAD * SEQ * SEQ]; // fallback if out lacks probs

__device__ __forceinline__ float atanh_c(float x) {
    x = fminf(fmaxf(x, -0.9999999f), 0.9999999f);
    return atanhf(x);
}
__device__ __forceinline__ float dot4(float4 a, float4 b) {
    return a.x * b.x + a.y * b.y + a.z * b.z + a.w * b.w;
}
__device__ __forceinline__ float warpsum(float v) {
    #pragma unroll
    for (int o = 16; o; o >>= 1) v += __shfl_xor_sync(0xffffffffu, v, o);
    return v;
}
__device__ __forceinline__ float grp4sum(float v) {   // sum within 4-lane groups
    v += __shfl_xor_sync(0xffffffffu, v, 1, 4);
    v += __shfl_xor_sync(0xffffffffu, v, 2, 4);
    return v;
}
__device__ __forceinline__ float blkred(float v, float* sm) {
    #pragma unroll
    for (int o = 16; o; o >>= 1) v += __shfl_xor_sync(0xffffffffu, v, o);
    if ((threadIdx.x & 31) == 0) sm[threadIdx.x >> 5] = v;
    __syncthreads();
    v = sm[0] + sm[1] + sm[2] + sm[3];
    __syncthreads();
    return v;
}

// ================= K1: mx = x @ W^T for q,k,v (scalar FFMA) =================
// A row r = b*256+s'  maps to query[(s'*B + b)*512 + k]
__global__ __launch_bounds__(256) void gemm_kernel(
    const float* __restrict__ query,
    const float* __restrict__ Wq,
    const float* __restrict__ Wk,
    const float* __restrict__ Wv)
{
    __shared__ float As[16][68];
    __shared__ float Bs[16][68];
    int mat = blockIdx.z;
    const float* W = (mat == 0) ? Wq : (mat == 1 ? Wk : Wv);
    float* out = g_mx + mat * NROW * HIDD;
    int t = threadIdx.x;
    int tx = t & 15, ty = t >> 4;
    int row0 = blockIdx.y << 6, col0 = blockIdx.x << 6;

    float acc[4][4];
    #pragma unroll
    for (int i = 0; i < 4; i++)
        #pragma unroll
        for (int j = 0; j < 4; j++) acc[i][j] = 0.f;

    for (int k0 = 0; k0 < HIDD; k0 += 16) {
        #pragma unroll
        for (int li = t; li < 1024; li += 256) {
            int i = li >> 4, kk = li & 15;
            int r = row0 + i;
            As[kk][i] = query[((((r & 255) << 1) + (r >> 8)) << 9) + k0 + kk];
            Bs[kk][i] = W[((col0 + i) << 9) + k0 + kk];
        }
        __syncthreads();
        #pragma unroll
        for (int kk = 0; kk < 16; kk++) {
            float4 a  = *(const float4*)&As[kk][ty << 2];
            float4 bb = *(const float4*)&Bs[kk][tx << 2];
            float av[4] = {a.x, a.y, a.z, a.w};
            float bv[4] = {bb.x, bb.y, bb.z, bb.w};
            #pragma unroll
            for (int i = 0; i < 4; i++)
                #pragma unroll
                for (int j = 0; j < 4; j++)
                    acc[i][j] = fmaf(av[i], bv[j], acc[i][j]);
        }
        __syncthreads();
    }
    #pragma unroll
    for (int i = 0; i < 4; i++) {
        float4 o = {acc[i][0], acc[i][1], acc[i][2], acc[i][3]};
        *(float4*)(out + ((row0 + (ty << 2) + i) << 9) + col0 + (tx << 2)) = o;
    }
}

// ===== K2: warp-per-row epilogue — shuffle-only reductions, no smem/syncs =====
__global__ __launch_bounds__(256) void epilogue_kernel(
    const float* __restrict__ query,
    const float* __restrict__ bq,
    const float* __restrict__ bk,
    const float* __restrict__ bv)
{
    int w = blockIdx.x * 8 + (threadIdx.x >> 5);   // global warp = row task
    int l = threadIdx.x & 31;
    int mat = w >> 9;            // 0..2
    int r = w & 511;             // b*256 + s'
    int b = r >> 8, sp = r & 255;
    const float* bias_p = (mat == 0) ? bq : (mat == 1 ? bk : bv);
    float* outp = (mat == 0) ? g_q : (mat == 1 ? g_k : g_v);

    const float4* xp = (const float4*)(query + ((sp * BATCH + b) << 9));
    const float4* mp = (const float4*)(g_mx + mat * NROW * HIDD + (r << 9));
    const float4* bp = (const float4*)bias_p;

    float4 x4[4], m4[4], bi4[4];
    #pragma unroll
    for (int j = 0; j < 4; j++) {
        x4[j]  = xp[4 * l + j];
        m4[j]  = mp[4 * l + j];
        bi4[j] = bp[4 * l + j];
    }

    float sxx = 0.f, smm = 0.f;
    #pragma unroll
    for (int j = 0; j < 4; j++) { sxx += dot4(x4[j], x4[j]); smm += dot4(m4[j], m4[j]); }
    sxx = warpsum(sxx);
    smm = warpsum(smm);
    float xn = fmaxf(sqrtf(sxx), EPSN);
    float mn = fmaxf(sqrtf(smm), EPSN);
    float sc1 = tanhf(mn / xn * atanh_c(xn)) / mn;

    float4 res[4];
    float x2 = 0.f, xy = 0.f, y2 = 0.f;
    #pragma unroll
    for (int j = 0; j < 4; j++) {
        res[j] = make_float4(sc1 * m4[j].x, sc1 * m4[j].y, sc1 * m4[j].z, sc1 * m4[j].w);
        x2 += dot4(res[j], res[j]);
        xy += dot4(res[j], bi4[j]);
        y2 += dot4(bi4[j], bi4[j]);
    }
    x2 = warpsum(x2); xy = warpsum(xy); y2 = warpsum(y2);
    float ac = 1.f + 2.f * xy + y2;
    float bc = 1.f - x2;
    float den = fmaxf(1.f + 2.f * xy + x2 * y2, EPSN);
    float idn = 1.f / den;

    float4 z4[4];
    float z2 = 0.f;
    #pragma unroll
    for (int j = 0; j < 4; j++) {
        z4[j] = make_float4((ac * res[j].x + bc * bi4[j].x) * idn,
                            (ac * res[j].y + bc * bi4[j].y) * idn,
                            (ac * res[j].z + bc * bi4[j].z) * idn,
                            (ac * res[j].w + bc * bi4[j].w) * idn);
        z2 += dot4(z4[j], z4[j]);
    }
    z2 = warpsum(z2);
    float nz = fmaxf(sqrtf(z2), EPSN);
    float ps = (nz > MAXNORM) ? (MAXNORM / nz) : 1.f;
    float nzc = nz * ps;                       // = min(nz, MAXNORM)
    float us = atanh_c(nzc) / fmaxf(nzc, EPSN) * ps;   // u = us * z

    float4 u4[4];
    float cs = 0.f;
    #pragma unroll
    for (int j = 0; j < 4; j++) {
        u4[j] = make_float4(us * z4[j].x, us * z4[j].y, us * z4[j].z, us * z4[j].w);
        cs += dot4(u4[j], u4[j]);
    }
    cs = grp4sum(cs);                          // 64-elem chunk = 4 lanes
    float cn = fmaxf(sqrtf(cs), EPSN);
    float csc = tanhf(cn) / cn;

    float4* op = (float4*)(outp + (r << 9));
    #pragma unroll
    for (int j = 0; j < 4; j++)
        op[4 * l + j] = make_float4(csc * u4[j].x, csc * u4[j].y, csc * u4[j].z, csc * u4[j].w);

    if ((l & 3) == 0) {
        float o2 = csc * csc * cs;             // |chunk|^2 of output
        int cid = b * CHB + sp * 8 + (l >> 2); // flat chunk id == h*256+s
        if (mat == 0)      g_q2[cid] = o2;
        else if (mat == 1) g_k2[cid] = o2;
        else               g_gamma[cid] = 2.f / fmaxf(1.f - o2, EPSN);
    }
}

// ===== K3 (fused): scores -> probs, then midpoint partial GEMM-let =====
// Phase A (identical math to R5 score): 64x64 probs tile; qsm freed to regs,
// probs also stored to smem (aliases qsm region).
// Phase B: nom[64q x 64d] partial = psm @ (gamma*v) with gamma*v aliasing ksm.
// Partial (nom, dacc) layout identical to previous ctx_kernel output.
__global__ __launch_bounds__(256, 2) void score_ctx_kernel(float* __restrict__ probs_ext)
{
    __shared__ float regA[64 * 68];   // qsm -> psm
    __shared__ float regB[64 * 68];   // ksm -> (gamma*v) as float4[64][17]
    __shared__ float q2s[64];
    __shared__ float k2s[64];
    __shared__ float gm1[64];
    float* probs = probs_ext ? probs_ext : g_probs;

    int bh = blockIdx.z;
    int b = bh >> 3, h = bh & 7;
    int q0 = blockIdx.y << 6, n0 = blockIdx.x << 6;
    int ns = blockIdx.x;               // n-split id for partials
    const float4* Qp = (const float4*)(g_q + b * 131072 + ((h << 8) + q0) * 64);
    const float4* Kp = (const float4*)(g_k + b * 131072 + ((h << 8) + n0) * 64);
    int t = threadIdx.x;

    for (int li = t; li < 1024; li += 256) {
        int row = li >> 4, c4 = li & 15;
        *(float4*)&regA[row * 68 + (c4 << 2)] = Qp[li];
        *(float4*)&regB[row * 68 + (c4 << 2)] = Kp[li];
    }
    if (t < 64) {
        q2s[t] = g_q2[b * CHB + (h << 8) + q0 + t];
        k2s[t] = g_k2[b * CHB + (h << 8) + n0 + t];
    }
    __syncthreads();

    int qi = t >> 2, nl = t & 3;
    float4 qr[16];
    #pragma unroll
    for (int i = 0; i < 16; i++) qr[i] = *(const float4*)&regA[qi * 68 + (i << 2)];
    float q2 = q2s[qi];
    float Bc = 1.f - q2;
    float* orow = probs + ((bh << 8) + q0 + qi) * 256 + n0;
    __syncthreads();                   // all qr loaded; regA may be overwritten

    #pragma unroll 1
    for (int jj = 0; jj < 8; jj++) {
        int na = (jj << 3) | nl;       // two n per iteration: na, na+4
        int nb = na + 4;
        // ---- pass 1: dot products (2 independent chains) ----
        float da = 0.f, db = 0.f;
        #pragma unroll
        for (int i = 0; i < 16; i++) {
            float4 ka = *(const float4*)&regB[na * 68 + (i << 2)];
            float4 kb = *(const float4*)&regB[nb * 68 + (i << 2)];
            da += dot4(qr[i], ka);
            db += dot4(qr[i], kb);
        }
        float k2a = k2s[na], k2b = k2s[nb];
        float Aa = 1.f - 2.f * da + k2a;
        float Ab = 1.f - 2.f * db + k2b;
        float dena = fmaxf(fmaf(q2, k2a, 1.f - 2.f * da), EPSN);
        float denb = fmaxf(fmaf(q2, k2b, 1.f - 2.f * db), EPSN);
        // ---- pass 2: sum of reciprocal squares, quad-combined ----
        float acca = 0.f, accb = 0.f;
        #pragma unroll
        for (int i = 0; i < 16; i++) {
            float4 q = qr[i];
            float4 ka = *(const float4*)&regB[na * 68 + (i << 2)];
            float4 kb = *(const float4*)&regB[nb * 68 + (i << 2)];
            {
                float w0 = fmaf(Bc, ka.x, -Aa * q.x);
                float w1 = fmaf(Bc, ka.y, -Aa * q.y);
                float w2 = fmaf(Bc, ka.z, -Aa * q.z);
                float w3 = fmaf(Bc, ka.w, -Aa * q.w);
                float x0 = w0 * w0, x1 = w1 * w1, x2 = w2 * w2, x3 = w3 * w3;
                float s01 = x0 + x1, s23 = x2 + x3;
                float p01 = x0 * x1, p23 = x2 * x3;
                float num = fmaf(s01, p23, s23 * p01);
                float dn4 = fmaxf(p01 * p23, 1e-37f);
                acca += __fdividef(num, dn4);
            }
            {
                float w0 = fmaf(Bc, kb.x, -Ab * q.x);
                float w1 = fmaf(Bc, kb.y, -Ab * q.y);
                float w2 = fmaf(Bc, kb.z, -Ab * q.z);
                float w3 = fmaf(Bc, kb.w, -Ab * q.w);
                float x0 = w0 * w0, x1 = w1 * w1, x2 = w2 * w2, x3 = w3 * w3;
                float s01 = x0 + x1, s23 = x2 + x3;
                float p01 = x0 * x1, p23 = x2 * x3;
                float num = fmaf(s01, p23, s23 * p01);
                float dn4 = fmaxf(p01 * p23, 1e-37f);
                accb += __fdividef(num, dn4);
            }
        }
        float t1a = __fdividef(rsqrtf(acca), dena);
        float t1b = __fdividef(rsqrtf(accb), denb);
        t1a = fminf(t1a, 0.9999999f);
        t1b = fminf(t1b, 0.9999999f);
        float pa = 0.5f - 0.5f * t1a;
        float pb = 0.5f - 0.5f * t1b;
        orow[na] = pa;
        orow[nb] = pb;
        regA[qi * 65 + na] = pa;       // psm (aliases qsm region, pad 65)
        regA[qi * 65 + nb] = pb;
    }
    __syncthreads();                   // probs tile complete; ksm no longer needed

    // ---- load gamma*v into regB as float4[64][17]; gm1 ----
    {
        const float* Vb  = g_v + b * 131072 + (h << 14);
        const float* gmb = g_gamma + b * CHB + (h << 8);
        for (int li = t; li < 1024; li += 256) {
            int n = li >> 4, d4 = li & 15;
            int gn = n0 + n;
            float g = gmb[gn];
            float4 v = *(const float4*)(Vb + (gn << 6) + (d4 << 2));
            ((float4*)regB)[n * 17 + d4] = make_float4(v.x * g, v.y * g, v.z * g, v.w * g);
        }
        if (t < 64) gm1[t] = gmb[n0 + t] - 1.f;
    }
    __syncthreads();

    // ---- phase B: 4 q-rows x float4-of-d per thread ----
    int qi2 = t >> 4, dh = t & 15;
    float4 acc[4];
    float dac[4];
    #pragma unroll
    for (int j = 0; j < 4; j++) { acc[j] = make_float4(0.f, 0.f, 0.f, 0.f); dac[j] = 0.f; }

    #pragma unroll 4
    for (int n = 0; n < 64; n++) {
        float4 v = ((const float4*)regB)[n * 17 + dh];
        float g1 = gm1[n];
        #pragma unroll
        for (int j = 0; j < 4; j++) {
            float p = regA[(qi2 + (j << 4)) * 65 + n];
            acc[j].x = fmaf(p, v.x, acc[j].x);
            acc[j].y = fmaf(p, v.y, acc[j].y);
            acc[j].z = fmaf(p, v.z, acc[j].z);
            acc[j].w = fmaf(p, v.w, acc[j].w);
            dac[j] = fmaf(p, g1, dac[j]);
        }
    }
    #pragma unroll
    for (int j = 0; j < 4; j++) {
        int row = (b << 8) + q0 + qi2 + (j << 4);
        *(float4*)(g_pnom + ((ns * NROW + row) << 9) + (h << 6) + (dh << 2)) = acc[j];
        if (dh == 0)
            g_pdac[((ns * NROW + row) << 3) + h] = dac[j];
    }
}

// ===== K5: reduce partials + gyro epilogue + final expmap0 + transpose =====
__global__ __launch_bounds__(128) void final_kernel(float* __restrict__ out)
{
    __shared__ float red[4];
    int row = blockIdx.x;          // b*256 + q
    int b = row >> 8, q = row & 255;
    int t = threadIdx.x;
    int h = t >> 4;

    float4 nom = {0.f, 0.f, 0.f, 0.f};
    float dacc = 0.f;
    #pragma unroll
    for (int ns = 0; ns < 4; ns++) {
        float4 pv = *(const float4*)(g_pnom + ((ns * NROW + row) << 9) + (t << 2));
        nom.x += pv.x; nom.y += pv.y; nom.z += pv.z; nom.w += pv.w;
        dacc += g_pdac[((ns * NROW + row) << 3) + h];
    }

    // denom sign/floor, ctx0 = nom/denom, then u = 0.5*atanh(|ctx0|)/|ctx0| * ctx0
    float dn = fmaxf(fabsf(dacc), 1e-10f);
    if (dacc < 0.f) dn = -dn;
    float idn = 1.f / dn;
    float4 c0 = {nom.x * idn, nom.y * idn, nom.z * idn, nom.w * idn};
    float ss = dot4(c0, c0);
    #pragma unroll
    for (int o = 8; o; o >>= 1) ss += __shfl_xor_sync(0xffffffffu, ss, o, 16);
    float nn = fmaxf(sqrtf(ss), EPSN);
    float usc = 0.5f * atanh_c(nn) / nn;
    float4 u = {usc * c0.x, usc * c0.y, usc * c0.z, usc * c0.w};

    // full-512 expmap0 + transpose to [S,B,HID]
    float s = blkred(dot4(u, u), red);
    float n512 = fmaxf(sqrtf(s), EPSN);
    float sc = tanhf(n512) / n512;
    float4 o = {sc * u.x, sc * u.y, sc * u.z, sc * u.w};
    *(float4*)(out + ((q * BATCH + b) << 9) + (t << 2)) = o;
}

// ---------------- launch ----------------
extern "C" void kernel_launch(void* const* d_in, const int* in_sizes, int n_in,
                              void* d_out, int out_size)
{
    const float* query = (const float*)d_in[0];
    const float* Wq = (const float*)d_in[1];
    const float* bq = (const float*)d_in[2];
    const float* Wk = (const float*)d_in[3];
    const float* bk = (const float*)d_in[4];
    const float* Wv = (const float*)d_in[5];
    const float* bv = (const float*)d_in[6];
    float* out = (float*)d_out;

    // output layout: ctx [S,B,HID] (262144) then probs [B,H,S,S] (1048576)
    float* probs = (out_size >= 262144 + 1048576) ? (out + 262144) : (float*)0;

    gemm_kernel<<<dim3(8, 8, 3), 256>>>(query, Wq, Wk, Wv);
    epilogue_kernel<<<192, 256>>>(query, bq, bk, bv);
    score_ctx_kernel<<<dim3(4, 4, 16), 256>>>(probs);
    final_kernel<<<512, 128>>>(out);
}

// round 14
// speedup vs baseline: 1.5540x; 1.2560x over previous
#include <cuda_runtime.h>
#include <math.h>

// ---------------- problem constants ----------------
#define SEQ   256
#define BATCH 2
#define HIDD  512
#define NHEAD 8
#define HDIM  64
#define NROW  512              // BATCH*SEQ
#define CHB   2048             // chunks per batch = SEQ*NHEAD
#define EPSN  1e-15f
#define MAXNORM 0.996f         // (1-4e-3)/sqrt(c), c=1

// ---------------- device scratch (static, allowed) ----------------
__device__ float g_mx[3 * NROW * HIDD];        // GEMM outputs (3 MB)
__device__ float g_q[NROW * HIDD];             // ql chunks, flat [b][s'][512]
__device__ float g_k[NROW * HIDD];
__device__ float g_v[NROW * HIDD];
__device__ float g_q2[BATCH * CHB];            // |ql chunk|^2
__device__ float g_k2[BATCH * CHB];
__device__ float g_gamma[BATCH * CHB];         // 2/max(1-|vl|^2,eps)
__device__ float g_pnom[4 * NROW * HIDD];      // ctx partial numerators (4 MB)
__device__ float g_pdac[4 * NROW * NHEAD];     // ctx partial denominators
__device__ float g_probs[BATCH * NHEAD * SEQ * SEQ]; // fallback if out lacks probs

// ---------------- packed f32x2 helpers ----------------
__device__ __forceinline__ float2 ffma2(float2 a, float2 b, float2 c) {
    unsigned long long ua = *(unsigned long long*)&a;
    unsigned long long ub = *(unsigned long long*)&b;
    unsigned long long uc = *(unsigned long long*)&c;
    unsigned long long ud;
    asm("fma.rn.f32x2 %0, %1, %2, %3;" : "=l"(ud) : "l"(ua), "l"(ub), "l"(uc));
    return *(float2*)&ud;
}
__device__ __forceinline__ float2 fmul2(float2 a, float2 b) {
    unsigned long long ua = *(unsigned long long*)&a;
    unsigned long long ub = *(unsigned long long*)&b;
    unsigned long long ud;
    asm("mul.rn.f32x2 %0, %1, %2;" : "=l"(ud) : "l"(ua), "l"(ub));
    return *(float2*)&ud;
}
__device__ __forceinline__ float2 fadd2(float2 a, float2 b) {
    unsigned long long ua = *(unsigned long long*)&a;
    unsigned long long ub = *(unsigned long long*)&b;
    unsigned long long ud;
    asm("add.rn.f32x2 %0, %1, %2;" : "=l"(ud) : "l"(ua), "l"(ub));
    return *(float2*)&ud;
}

__device__ __forceinline__ float atanh_c(float x) {
    x = fminf(fmaxf(x, -0.9999999f), 0.9999999f);
    return atanhf(x);
}
__device__ __forceinline__ float dot4(float4 a, float4 b) {
    return a.x * b.x + a.y * b.y + a.z * b.z + a.w * b.w;
}
__device__ __forceinline__ float warpsum(float v) {
    #pragma unroll
    for (int o = 16; o; o >>= 1) v += __shfl_xor_sync(0xffffffffu, v, o);
    return v;
}
__device__ __forceinline__ float grp4sum(float v) {   // sum within 4-lane groups
    v += __shfl_xor_sync(0xffffffffu, v, 1, 4);
    v += __shfl_xor_sync(0xffffffffu, v, 2, 4);
    return v;
}
__device__ __forceinline__ float blkred(float v, float* sm) {
    #pragma unroll
    for (int o = 16; o; o >>= 1) v += __shfl_xor_sync(0xffffffffu, v, o);
    if ((threadIdx.x & 31) == 0) sm[threadIdx.x >> 5] = v;
    __syncthreads();
    v = sm[0] + sm[1] + sm[2] + sm[3];
    __syncthreads();
    return v;
}

// ================= K1: mx = x @ W^T for q,k,v (scalar FFMA) =================
__global__ __launch_bounds__(256) void gemm_kernel(
    const float* __restrict__ query,
    const float* __restrict__ Wq,
    const float* __restrict__ Wk,
    const float* __restrict__ Wv)
{
    __shared__ float As[16][68];
    __shared__ float Bs[16][68];
    int mat = blockIdx.z;
    const float* W = (mat == 0) ? Wq : (mat == 1 ? Wk : Wv);
    float* out = g_mx + mat * NROW * HIDD;
    int t = threadIdx.x;
    int tx = t & 15, ty = t >> 4;
    int row0 = blockIdx.y << 6, col0 = blockIdx.x << 6;

    float acc[4][4];
    #pragma unroll
    for (int i = 0; i < 4; i++)
        #pragma unroll
        for (int j = 0; j < 4; j++) acc[i][j] = 0.f;

    for (int k0 = 0; k0 < HIDD; k0 += 16) {
        #pragma unroll
        for (int li = t; li < 1024; li += 256) {
            int i = li >> 4, kk = li & 15;
            int r = row0 + i;
            As[kk][i] = query[((((r & 255) << 1) + (r >> 8)) << 9) + k0 + kk];
            Bs[kk][i] = W[((col0 + i) << 9) + k0 + kk];
        }
        __syncthreads();
        #pragma unroll
        for (int kk = 0; kk < 16; kk++) {
            float4 a  = *(const float4*)&As[kk][ty << 2];
            float4 bb = *(const float4*)&Bs[kk][tx << 2];
            float av[4] = {a.x, a.y, a.z, a.w};
            float bv[4] = {bb.x, bb.y, bb.z, bb.w};
            #pragma unroll
            for (int i = 0; i < 4; i++)
                #pragma unroll
                for (int j = 0; j < 4; j++)
                    acc[i][j] = fmaf(av[i], bv[j], acc[i][j]);
        }
        __syncthreads();
    }
    #pragma unroll
    for (int i = 0; i < 4; i++) {
        float4 o = {acc[i][0], acc[i][1], acc[i][2], acc[i][3]};
        *(float4*)(out + ((row0 + (ty << 2) + i) << 9) + col0 + (tx << 2)) = o;
    }
}

// ===== K2: warp-per-row epilogue — shuffle-only reductions =====
__global__ __launch_bounds__(256) void epilogue_kernel(
    const float* __restrict__ query,
    const float* __restrict__ bq,
    const float* __restrict__ bk,
    const float* __restrict__ bv)
{
    int w = blockIdx.x * 8 + (threadIdx.x >> 5);   // global warp = row task
    int l = threadIdx.x & 31;
    int mat = w >> 9;            // 0..2
    int r = w & 511;             // b*256 + s'
    int b = r >> 8, sp = r & 255;
    const float* bias_p = (mat == 0) ? bq : (mat == 1 ? bk : bv);
    float* outp = (mat == 0) ? g_q : (mat == 1 ? g_k : g_v);

    const float4* xp = (const float4*)(query + ((sp * BATCH + b) << 9));
    const float4* mp = (const float4*)(g_mx + mat * NROW * HIDD + (r << 9));
    const float4* bp = (const float4*)bias_p;

    float4 x4[4], m4[4], bi4[4];
    #pragma unroll
    for (int j = 0; j < 4; j++) {
        x4[j]  = xp[4 * l + j];
        m4[j]  = mp[4 * l + j];
        bi4[j] = bp[4 * l + j];
    }

    float sxx = 0.f, smm = 0.f;
    #pragma unroll
    for (int j = 0; j < 4; j++) { sxx += dot4(x4[j], x4[j]); smm += dot4(m4[j], m4[j]); }
    sxx = warpsum(sxx);
    smm = warpsum(smm);
    float xn = fmaxf(sqrtf(sxx), EPSN);
    float mn = fmaxf(sqrtf(smm), EPSN);
    float sc1 = tanhf(mn / xn * atanh_c(xn)) / mn;

    float4 res[4];
    float x2 = 0.f, xy = 0.f, y2 = 0.f;
    #pragma unroll
    for (int j = 0; j < 4; j++) {
        res[j] = make_float4(sc1 * m4[j].x, sc1 * m4[j].y, sc1 * m4[j].z, sc1 * m4[j].w);
        x2 += dot4(res[j], res[j]);
        xy += dot4(res[j], bi4[j]);
        y2 += dot4(bi4[j], bi4[j]);
    }
    x2 = warpsum(x2); xy = warpsum(xy); y2 = warpsum(y2);
    float ac = 1.f + 2.f * xy + y2;
    float bc = 1.f - x2;
    float den = fmaxf(1.f + 2.f * xy + x2 * y2, EPSN);
    float idn = 1.f / den;

    float4 z4[4];
    float z2 = 0.f;
    #pragma unroll
    for (int j = 0; j < 4; j++) {
        z4[j] = make_float4((ac * res[j].x + bc * bi4[j].x) * idn,
                            (ac * res[j].y + bc * bi4[j].y) * idn,
                            (ac * res[j].z + bc * bi4[j].z) * idn,
                            (ac * res[j].w + bc * bi4[j].w) * idn);
        z2 += dot4(z4[j], z4[j]);
    }
    z2 = warpsum(z2);
    float nz = fmaxf(sqrtf(z2), EPSN);
    float ps = (nz > MAXNORM) ? (MAXNORM / nz) : 1.f;
    float nzc = nz * ps;                       // = min(nz, MAXNORM)
    float us = atanh_c(nzc) / fmaxf(nzc, EPSN) * ps;   // u = us * z

    float4 u4[4];
    float cs = 0.f;
    #pragma unroll
    for (int j = 0; j < 4; j++) {
        u4[j] = make_float4(us * z4[j].x, us * z4[j].y, us * z4[j].z, us * z4[j].w);
        cs += dot4(u4[j], u4[j]);
    }
    cs = grp4sum(cs);                          // 64-elem chunk = 4 lanes
    float cn = fmaxf(sqrtf(cs), EPSN);
    float csc = tanhf(cn) / cn;

    float4* op = (float4*)(outp + (r << 9));
    #pragma unroll
    for (int j = 0; j < 4; j++)
        op[4 * l + j] = make_float4(csc * u4[j].x, csc * u4[j].y, csc * u4[j].z, csc * u4[j].w);

    if ((l & 3) == 0) {
        float o2 = csc * csc * cs;             // |chunk|^2 of output
        int cid = b * CHB + sp * 8 + (l >> 2); // flat chunk id == h*256+s
        if (mat == 0)      g_q2[cid] = o2;
        else if (mat == 1) g_k2[cid] = o2;
        else               g_gamma[cid] = 2.f / fmaxf(1.f - o2, EPSN);
    }
}

// ===== K3 (fused): scores -> probs, then midpoint partial GEMM-let =====
// Phase A packed-f32x2 + Bc factoring:
//   w_d = Bc*k_d - A*q_d = Bc * (k_d - r*q_d),  r = A/Bc  (Bc > 0 in the ball)
//   t1 = Bc * rsqrt(sum_d 1/w'_d^2) / den
// quad-combine in packed form -> 1 RCP per 4 d.
__global__ __launch_bounds__(256, 2) void score_ctx_kernel(float* __restrict__ probs_ext)
{
    __shared__ float regA[64 * 68];   // qsm -> psm
    __shared__ float regB[64 * 68];   // ksm -> (gamma*v) as float4[64][17]
    __shared__ float q2s[64];
    __shared__ float k2s[64];
    __shared__ float gm1[64];
    float* probs = probs_ext ? probs_ext : g_probs;

    int bh = blockIdx.z;
    int b = bh >> 3, h = bh & 7;
    int q0 = blockIdx.y << 6, n0 = blockIdx.x << 6;
    int ns = blockIdx.x;               // n-split id for partials
    const float4* Qp = (const float4*)(g_q + b * 131072 + ((h << 8) + q0) * 64);
    const float4* Kp = (const float4*)(g_k + b * 131072 + ((h << 8) + n0) * 64);
    int t = threadIdx.x;

    for (int li = t; li < 1024; li += 256) {
        int row = li >> 4, c4 = li & 15;
        *(float4*)&regA[row * 68 + (c4 << 2)] = Qp[li];
        *(float4*)&regB[row * 68 + (c4 << 2)] = Kp[li];
    }
    if (t < 64) {
        q2s[t] = g_q2[b * CHB + (h << 8) + q0 + t];
        k2s[t] = g_k2[b * CHB + (h << 8) + n0 + t];
    }
    __syncthreads();

    int qi = t >> 2, nl = t & 3;
    float4 qr[16];
    #pragma unroll
    for (int i = 0; i < 16; i++) qr[i] = *(const float4*)&regA[qi * 68 + (i << 2)];
    float q2 = q2s[qi];
    float Bc = 1.f - q2;
    float invBc = 1.f / Bc;
    float* orow = probs + ((bh << 8) + q0 + qi) * 256 + n0;
    __syncthreads();                   // all qr loaded; regA may be overwritten

    #pragma unroll 1
    for (int jj = 0; jj < 8; jj++) {
        int na = (jj << 3) | nl;       // two n per iteration: na, na+4
        int nb = na + 4;
        // ---- pass 1: dot products, packed (4 independent chains) ----
        float2 sa0 = make_float2(0.f, 0.f), sa1 = make_float2(0.f, 0.f);
        float2 sb0 = make_float2(0.f, 0.f), sb1 = make_float2(0.f, 0.f);
        #pragma unroll
        for (int i = 0; i < 16; i++) {
            float4 q = qr[i];
            float4 ka = *(const float4*)&regB[na * 68 + (i << 2)];
            float4 kb = *(const float4*)&regB[nb * 68 + (i << 2)];
            sa0 = ffma2(make_float2(q.x, q.y), make_float2(ka.x, ka.y), sa0);
            sa1 = ffma2(make_float2(q.z, q.w), make_float2(ka.z, ka.w), sa1);
            sb0 = ffma2(make_float2(q.x, q.y), make_float2(kb.x, kb.y), sb0);
            sb1 = ffma2(make_float2(q.z, q.w), make_float2(kb.z, kb.w), sb1);
        }
        float da = sa0.x + sa0.y + sa1.x + sa1.y;
        float db = sb0.x + sb0.y + sb1.x + sb1.y;
        float k2a = k2s[na], k2b = k2s[nb];
        float Aa = 1.f - 2.f * da + k2a;
        float Ab = 1.f - 2.f * db + k2b;
        float dena = fmaxf(fmaf(q2, k2a, 1.f - 2.f * da), EPSN);
        float denb = fmaxf(fmaf(q2, k2b, 1.f - 2.f * db), EPSN);
        float ra = Aa * invBc;
        float rb = Ab * invBc;
        float2 mra = make_float2(-ra, -ra);    // hoisted packs (once per jj)
        float2 mrb = make_float2(-rb, -rb);
        // ---- pass 2: sum of reciprocal squares, packed quad-combine ----
        float acca = 0.f, accb = 0.f;
        #pragma unroll
        for (int i = 0; i < 16; i++) {
            float4 q = qr[i];
            float2 q01 = make_float2(q.x, q.y);
            float2 q23 = make_float2(q.z, q.w);
            float4 ka = *(const float4*)&regB[na * 68 + (i << 2)];
            float4 kb = *(const float4*)&regB[nb * 68 + (i << 2)];
            {
                float2 w01 = ffma2(mra, q01, make_float2(ka.x, ka.y));  // k - r*q
                float2 w23 = ffma2(mra, q23, make_float2(ka.z, ka.w));
                float2 x01 = fmul2(w01, w01);
                float2 x23 = fmul2(w23, w23);
                float2 s2 = fadd2(x01, x23);   // (x0+x2, x1+x3)
                float2 p2 = fmul2(x01, x23);   // (x0*x2, x1*x3)
                float num = fmaf(s2.x, p2.y, s2.y * p2.x);
                float dn4 = fmaxf(p2.x * p2.y, 1e-37f);
                acca += __fdividef(num, dn4);
            }
            {
                float2 w01 = ffma2(mrb, q01, make_float2(kb.x, kb.y));
                float2 w23 = ffma2(mrb, q23, make_float2(kb.z, kb.w));
                float2 x01 = fmul2(w01, w01);
                float2 x23 = fmul2(w23, w23);
                float2 s2 = fadd2(x01, x23);
                float2 p2 = fmul2(x01, x23);
                float num = fmaf(s2.x, p2.y, s2.y * p2.x);
                float dn4 = fmaxf(p2.x * p2.y, 1e-37f);
                accb += __fdividef(num, dn4);
            }
        }
        float t1a = __fdividef(Bc * rsqrtf(acca), dena);
        float t1b = __fdividef(Bc * rsqrtf(accb), denb);
        t1a = fminf(t1a, 0.9999999f);
        t1b = fminf(t1b, 0.9999999f);
        float pa = 0.5f - 0.5f * t1a;
        float pb = 0.5f - 0.5f * t1b;
        orow[na] = pa;
        orow[nb] = pb;
        regA[qi * 65 + na] = pa;       // psm (aliases qsm region, pad 65)
        regA[qi * 65 + nb] = pb;
    }
    __syncthreads();                   // probs tile complete; ksm no longer needed

    // ---- load gamma*v into regB as float4[64][17]; gm1 ----
    {
        const float* Vb  = g_v + b * 131072 + (h << 14);
        const float* gmb = g_gamma + b * CHB + (h << 8);
        for (int li = t; li < 1024; li += 256) {
            int n = li >> 4, d4 = li & 15;
            int gn = n0 + n;
            float g = gmb[gn];
            float4 v = *(const float4*)(Vb + (gn << 6) + (d4 << 2));
            ((float4*)regB)[n * 17 + d4] = make_float4(v.x * g, v.y * g, v.z * g, v.w * g);
        }
        if (t < 64) gm1[t] = gmb[n0 + t] - 1.f;
    }
    __syncthreads();

    // ---- phase B: 4 q-rows x float4-of-d per thread ----
    int qi2 = t >> 4, dh = t & 15;
    float4 acc[4];
    float dac[4];
    #pragma unroll
    for (int j = 0; j < 4; j++) { acc[j] = make_float4(0.f, 0.f, 0.f, 0.f); dac[j] = 0.f; }

    #pragma unroll 4
    for (int n = 0; n < 64; n++) {
        float4 v = ((const float4*)regB)[n * 17 + dh];
        float g1 = gm1[n];
        #pragma unroll
        for (int j = 0; j < 4; j++) {
            float p = regA[(qi2 + (j << 4)) * 65 + n];
            acc[j].x = fmaf(p, v.x, acc[j].x);
            acc[j].y = fmaf(p, v.y, acc[j].y);
            acc[j].z = fmaf(p, v.z, acc[j].z);
            acc[j].w = fmaf(p, v.w, acc[j].w);
            dac[j] = fmaf(p, g1, dac[j]);
        }
    }
    #pragma unroll
    for (int j = 0; j < 4; j++) {
        int row = (b << 8) + q0 + qi2 + (j << 4);
        *(float4*)(g_pnom + ((ns * NROW + row) << 9) + (h << 6) + (dh << 2)) = acc[j];
        if (dh == 0)
            g_pdac[((ns * NROW + row) << 3) + h] = dac[j];
    }
}

// ===== K5: reduce partials + gyro epilogue + final expmap0 + transpose =====
__global__ __launch_bounds__(128) void final_kernel(float* __restrict__ out)
{
    __shared__ float red[4];
    int row = blockIdx.x;          // b*256 + q
    int b = row >> 8, q = row & 255;
    int t = threadIdx.x;
    int h = t >> 4;

    float4 nom = {0.f, 0.f, 0.f, 0.f};
    float dacc = 0.f;
    #pragma unroll
    for (int ns = 0; ns < 4; ns++) {
        float4 pv = *(const float4*)(g_pnom + ((ns * NROW + row) << 9) + (t << 2));
        nom.x += pv.x; nom.y += pv.y; nom.z += pv.z; nom.w += pv.w;
        dacc += g_pdac[((ns * NROW + row) << 3) + h];
    }

    float dn = fmaxf(fabsf(dacc), 1e-10f);
    if (dacc < 0.f) dn = -dn;
    float idn = 1.f / dn;
    float4 c0 = {nom.x * idn, nom.y * idn, nom.z * idn, nom.w * idn};
    float ss = dot4(c0, c0);
    #pragma unroll
    for (int o = 8; o; o >>= 1) ss += __shfl_xor_sync(0xffffffffu, ss, o, 16);
    float nn = fmaxf(sqrtf(ss), EPSN);
    float usc = 0.5f * atanh_c(nn) / nn;
    float4 u = {usc * c0.x, usc * c0.y, usc * c0.z, usc * c0.w};

    float s = blkred(dot4(u, u), red);
    float n512 = fmaxf(sqrtf(s), EPSN);
    float sc = tanhf(n512) / n512;
    float4 o = {sc * u.x, sc * u.y, sc * u.z, sc * u.w};
    *(float4*)(out + ((q * BATCH + b) << 9) + (t << 2)) = o;
}

// ---------------- launch ----------------
extern "C" void kernel_launch(void* const* d_in, const int* in_sizes, int n_in,
                              void* d_out, int out_size)
{
    const float* query = (const float*)d_in[0];
    const float* Wq = (const float*)d_in[1];
    const float* bq = (const float*)d_in[2];
    const float* Wk = (const float*)d_in[3];
    const float* bk = (const float*)d_in[4];
    const float* Wv = (const float*)d_in[5];
    const float* bv = (const float*)d_in[6];
    float* out = (float*)d_out;

    // output layout: ctx [S,B,HID] (262144) then probs [B,H,S,S] (1048576)
    float* probs = (out_size >= 262144 + 1048576) ? (out + 262144) : (float*)0;

    gemm_kernel<<<dim3(8, 8, 3), 256>>>(query, Wq, Wk, Wv);
    epilogue_kernel<<<192, 256>>>(query, bq, bk, bv);
    score_ctx_kernel<<<dim3(4, 4, 16), 256>>>(probs);
    final_kernel<<<512, 128>>>(out);
}